// round 12
// baseline (speedup 1.0000x reference)
#include <cuda_runtime.h>
#include <cuda_fp16.h>
#include <cstdint>
#include <cstring>

#define H 256
#define NMAX 204800
#define BMAX 4096

__device__ float  g_e[NMAX];           // e scores, then alpha (in-place)
__device__ int    g_seg[NMAX];         // segment id per row
__device__ float  g_rst[BMAX * H];
__device__ int    g_off[BMAX + 1];
__device__ __half g_Wh[256 * 512];     // [col j][Wu row j | Wv row j]
__device__ float  g_Wr[H * H];         // tf32-RNA rounded Wout

// ---------------------------------------------------------------------------
// helpers
// ---------------------------------------------------------------------------
__device__ __forceinline__ uint32_t h2u(__half2 h) {
    uint32_t u;
    memcpy(&u, &h, 4);
    return u;
}
__device__ __forceinline__ void cpa16(uint32_t dst, const void* src) {
    asm volatile("cp.async.cg.shared.global [%0], [%1], 16;\n" :: "r"(dst), "l"(src));
}
#define CP_COMMIT() asm volatile("cp.async.commit_group;\n" ::: "memory")
#define CP_WAIT0()  asm volatile("cp.async.wait_group 0;\n" ::: "memory")
#define CP_WAIT1()  asm volatile("cp.async.wait_group 1;\n" ::: "memory")

__device__ __forceinline__ void mma_f16(float& d0, float& d1, float& d2, float& d3,
                                        uint32_t a0, uint32_t a1, uint32_t a2, uint32_t a3,
                                        uint32_t b0, uint32_t b1) {
    asm volatile("mma.sync.aligned.m16n8k16.row.col.f32.f16.f16.f32 "
                 "{%0,%1,%2,%3},{%4,%5,%6,%7},{%8,%9},{%0,%1,%2,%3};\n"
                 : "+f"(d0), "+f"(d1), "+f"(d2), "+f"(d3)
                 : "r"(a0), "r"(a1), "r"(a2), "r"(a3), "r"(b0), "r"(b1));
}
__device__ __forceinline__ void mma_tf32(float& d0, float& d1, float& d2, float& d3,
                                         uint32_t a0, uint32_t a1, uint32_t a2, uint32_t a3,
                                         uint32_t b0, uint32_t b1) {
    asm volatile("mma.sync.aligned.m16n8k8.row.col.f32.tf32.tf32.f32 "
                 "{%0,%1,%2,%3},{%4,%5,%6,%7},{%8,%9},{%0,%1,%2,%3};\n"
                 : "+f"(d0), "+f"(d1), "+f"(d2), "+f"(d3)
                 : "r"(a0), "r"(a1), "r"(a2), "r"(a3), "r"(b0), "r"(b1));
}
__device__ __forceinline__ void ldsm_x4(uint32_t& r0, uint32_t& r1, uint32_t& r2, uint32_t& r3,
                                        uint32_t addr) {
    asm volatile("ldmatrix.sync.aligned.m8n8.x4.shared.b16 {%0,%1,%2,%3}, [%4];"
                 : "=r"(r0), "=r"(r1), "=r"(r2), "=r"(r3) : "r"(addr));
}

// ---------------------------------------------------------------------------
// Prefix scan of ragged lengths (runtime int32/int64 detection).
// ---------------------------------------------------------------------------
__global__ __launch_bounds__(1024) void scan_kernel(const void* lens_raw, int b, int n_total) {
    __shared__ long long s[1024];
    __shared__ int use64;
    const int tid = threadIdx.x;
    const int* p32 = (const int*)lens_raw;

    long long local = 0;
    for (int i = tid; i < b; i += 1024) local += (long long)p32[i];
    s[tid] = local;
    __syncthreads();
    for (int o = 512; o > 0; o >>= 1) {
        if (tid < o) s[tid] += s[tid + o];
        __syncthreads();
    }
    if (tid == 0) use64 = (s[0] == (long long)n_total) ? 0 : 1;
    __syncthreads();
    const int u64 = use64;
    __syncthreads();

    const int PER = 4;
    long long v[PER];
    long long loc = 0;
    #pragma unroll
    for (int q = 0; q < PER; q++) {
        int i = tid * PER + q;
        long long val = 0;
        if (i < b) val = u64 ? ((const long long*)lens_raw)[i] : (long long)p32[i];
        v[q] = val;
        loc += val;
    }
    s[tid] = loc;
    __syncthreads();
    for (int o = 1; o < 1024; o <<= 1) {
        long long t = (tid >= o) ? s[tid - o] : 0;
        __syncthreads();
        s[tid] += t;
        __syncthreads();
    }
    long long run = s[tid] - loc;
    #pragma unroll
    for (int q = 0; q < PER; q++) {
        int i = tid * PER + q;
        if (i < b) {
            g_off[i] = (int)run;
            run += v[q];
            if (i == b - 1) g_off[b] = (int)run;
        }
    }
}

// ---------------------------------------------------------------------------
// Weight prep: fp16 [Wu|Wv] K-major per output col; tf32-RNA Wout.
// ---------------------------------------------------------------------------
__global__ __launch_bounds__(256) void conv_w_kernel(
    const float* __restrict__ Wu, const float* __restrict__ Wv, const float* __restrict__ Wout)
{
    const int j = blockIdx.x, k = threadIdx.x;
    g_Wh[j * 512 + k]       = __float2half_rn(Wu[j * H + k]);
    g_Wh[j * 512 + 256 + k] = __float2half_rn(Wv[j * H + k]);
    uint32_t c;
    asm("cvt.rna.tf32.f32 %0, %1;" : "=r"(c) : "f"(Wout[j * H + k]));
    g_Wr[j * H + k] = __uint_as_float(c);
}

// ---------------------------------------------------------------------------
// Fused e-GEMM, fp16 m16n8k16, LDSM fragments, 2 CTAs/SM (32 warps).
// BM=64, BN=256, K=512, BK=32. 256 threads, 8 warps 2x4; warp tile 32x64.
// SMEM: A bufs 2x5120 @0 | B bufs 2x20480 @10240 | sbu @51200 | sWe @52224 |
//       ered @53248 | total 54272. Tiles pitch 40 halfs (80 B).
// ---------------------------------------------------------------------------
#define EPS_B   10240
#define EPS_BU  51200
#define EPS_WE  52224
#define EPS_ER  53248
#define EPS_TOT 54272

__global__ __launch_bounds__(256, 2) void e_gemm_f16(
    const float* __restrict__ feats, const float* __restrict__ ctx,
    const float* __restrict__ bu, const float* __restrict__ We, int n)
{
    extern __shared__ char smc[];
    const uint32_t smb = (uint32_t)__cvta_generic_to_shared(smc);
    float* sbu  = (float*)(smc + EPS_BU);
    float* sWe  = (float*)(smc + EPS_WE);
    float* ered = (float*)(smc + EPS_ER);   // [64][4]

    const int tid  = threadIdx.x;
    const int lane = tid & 31;
    const int warp = tid >> 5;
    const int wm = warp >> 2;     // 0..1
    const int wn = warp & 3;      // 0..3
    const int g  = lane >> 2;
    const int t4 = lane & 3;
    const int row0 = blockIdx.x * 64;

    // A loader: thread -> row r (0..63), k-chunk c (0..3) of 8 halfs
    const int ar = tid >> 2;
    const int ac = tid & 3;
    int arow = row0 + ar; if (arow >= n) arow = n - 1;

    float acc[2][8][4];
    #pragma unroll
    for (int mi = 0; mi < 2; mi++)
        #pragma unroll
        for (int ni = 0; ni < 8; ni++)
            #pragma unroll
            for (int q = 0; q < 4; q++) acc[mi][ni][q] = 0.f;

    float4 avA, avB;

    auto ldgA = [&](int sidx) {
        const int k0 = sidx * 32;
        const float* Ap = (k0 < 256) ? feats : ctx;
        const float* p = Ap + (size_t)arow * H + (k0 & 255) + ac * 8;
        avA = *(const float4*)p;
        avB = *(const float4*)(p + 4);
    };
    auto stsA = [&](int buf) {
        uint4 u;
        u.x = h2u(__floats2half2_rn(avA.x, avA.y));
        u.y = h2u(__floats2half2_rn(avA.z, avA.w));
        u.z = h2u(__floats2half2_rn(avB.x, avB.y));
        u.w = h2u(__floats2half2_rn(avB.z, avB.w));
        *(uint4*)(smc + buf * 5120 + ar * 80 + ac * 16) = u;
    };
    auto issueB = [&](int buf, int sidx) {
        const int k0 = sidx * 32;
        #pragma unroll
        for (int q = 0; q < 4; q++) {   // 256 cols x 4 chunks -> 1024, 4/thread
            int idx = tid + q * 256;
            int j = idx >> 2, c = idx & 3;
            cpa16(smb + (uint32_t)(EPS_B + buf * 20480 + j * 80 + c * 16),
                  g_Wh + (size_t)j * 512 + k0 + c * 8);
        }
        CP_COMMIT();
    };

    const int a_row_in = (lane & 15);
    const int a_koff   = (lane >> 4) * 8;
    const int b_col_in = ((lane >> 4) & 1) * 8 + (lane & 7);
    const int b_koff   = ((lane >> 3) & 1) * 8;

    ldgA(0); stsA(0);
    issueB(0, 0);
    sbu[tid] = bu[tid];
    sWe[tid] = We[tid];

    for (int s = 0; s < 16; s++) {
        if (s + 1 < 16) { ldgA(s + 1); issueB((s + 1) & 1, s + 1); CP_WAIT1(); }
        else            { CP_WAIT0(); }
        __syncthreads();

        const uint32_t abase = smb + (s & 1) * 5120;
        const uint32_t bbase = smb + EPS_B + (s & 1) * 20480;

        #pragma unroll
        for (int kc = 0; kc < 2; kc++) {
            const int kw = kc * 16;
            uint32_t af[2][4];
            #pragma unroll
            for (int mi = 0; mi < 2; mi++) {
                ldsm_x4(af[mi][0], af[mi][1], af[mi][2], af[mi][3],
                        abase + (uint32_t)((wm * 32 + mi * 16 + a_row_in) * 80
                                           + (kw + a_koff) * 2));
            }
            uint32_t bf[8][2];
            #pragma unroll
            for (int n2 = 0; n2 < 4; n2++) {
                ldsm_x4(bf[n2 * 2][0], bf[n2 * 2][1], bf[n2 * 2 + 1][0], bf[n2 * 2 + 1][1],
                        bbase + (uint32_t)((wn * 64 + n2 * 16 + b_col_in) * 80
                                           + (kw + b_koff) * 2));
            }
            #pragma unroll
            for (int mi = 0; mi < 2; mi++)
                #pragma unroll
                for (int ni = 0; ni < 8; ni++)
                    mma_f16(acc[mi][ni][0], acc[mi][ni][1], acc[mi][ni][2], acc[mi][ni][3],
                            af[mi][0], af[mi][1], af[mi][2], af[mi][3],
                            bf[ni][0], bf[ni][1]);
        }
        if (s + 1 < 16) stsA((s + 1) & 1);
    }

    // Epilogue: sigmoid(h+bu)·We, row partials across wn
    float part[4] = {0.f, 0.f, 0.f, 0.f};
    #pragma unroll
    for (int mi = 0; mi < 2; mi++) {
        #pragma unroll
        for (int ni = 0; ni < 8; ni++) {
            const int c0 = wn * 64 + ni * 8 + t4 * 2;
            const int c1 = c0 + 1;
            const float w0 = sWe[c0], w1 = sWe[c1];
            const float b0 = sbu[c0], b1 = sbu[c1];
            float x;
            x = acc[mi][ni][0] + b0; part[mi * 2 + 0] += w0 / (1.f + __expf(-x));
            x = acc[mi][ni][1] + b1; part[mi * 2 + 0] += w1 / (1.f + __expf(-x));
            x = acc[mi][ni][2] + b0; part[mi * 2 + 1] += w0 / (1.f + __expf(-x));
            x = acc[mi][ni][3] + b1; part[mi * 2 + 1] += w1 / (1.f + __expf(-x));
        }
    }
    #pragma unroll
    for (int o = 1; o <= 2; o <<= 1)
        #pragma unroll
        for (int p = 0; p < 4; p++)
            part[p] += __shfl_xor_sync(0xffffffffu, part[p], o);
    if (t4 == 0) {
        #pragma unroll
        for (int p = 0; p < 4; p++) {
            int rl = wm * 32 + (p >> 1) * 16 + (p & 1) * 8 + g;
            ered[rl * 4 + wn] = part[p];
        }
    }
    __syncthreads();
    if (tid < 64) {
        int row = row0 + tid;
        if (row < n)
            g_e[row] = ered[tid * 4 + 0] + ered[tid * 4 + 1] + ered[tid * 4 + 2] + ered[tid * 4 + 3];
    }
}

// ---------------------------------------------------------------------------
// Zero g_rst (atomic accumulation target).
// ---------------------------------------------------------------------------
__global__ __launch_bounds__(1024) void zero_rst_kernel(int total4) {
    int i = blockIdx.x * 1024 + threadIdx.x;
    if (i < total4) ((float4*)g_rst)[i] = make_float4(0.f, 0.f, 0.f, 0.f);
}

// ---------------------------------------------------------------------------
// One WARP per segment: softmax over g_e in place (alpha), write seg ids.
// ---------------------------------------------------------------------------
__global__ __launch_bounds__(256) void alpha_kernel(int b) {
    const int seg = blockIdx.x * 8 + (threadIdx.x >> 5);
    if (seg >= b) return;
    const int lane = threadIdx.x & 31;
    const int base = g_off[seg];
    const int len  = g_off[seg + 1] - base;
    if (len <= 0) return;

    float m = -1e30f;
    for (int i = lane; i < len; i += 32) m = fmaxf(m, g_e[base + i]);
    #pragma unroll
    for (int o = 16; o > 0; o >>= 1) m = fmaxf(m, __shfl_xor_sync(0xffffffffu, m, o));

    float d = 0.f;
    for (int i = lane; i < len; i += 32) d += __expf(g_e[base + i] - m);
    #pragma unroll
    for (int o = 16; o > 0; o >>= 1) d += __shfl_xor_sync(0xffffffffu, d, o);
    const float inv = 1.f / d;

    for (int i = lane; i < len; i += 32) {
        g_e[base + i] = __expf(g_e[base + i] - m) * inv;
        g_seg[base + i] = seg;
    }
}

// ---------------------------------------------------------------------------
// Flat weighted pooling: 64 global rows per block, streaming, atomic flush
// at segment boundaries. thread = (row-group r4, column quad cq).
// ---------------------------------------------------------------------------
__global__ __launch_bounds__(256) void pool_flat_kernel(const float* __restrict__ feats, int n) {
    const int tid = threadIdx.x;
    const int r4 = tid >> 6;        // 0..3
    const int cq = tid & 63;        // 0..63
    const int row0 = blockIdx.x * 64 + r4;
    if (row0 >= n) return;
    const float* fcol = feats + cq * 4;

    int cur = g_seg[row0];
    float4 acc = make_float4(0.f, 0.f, 0.f, 0.f);

    #pragma unroll
    for (int j0 = 0; j0 < 16; j0 += 4) {
        float4 v[4]; float a[4]; int sg[4];
        #pragma unroll
        for (int k = 0; k < 4; k++) {
            int row = row0 + (j0 + k) * 4;
            bool ok = row < n;
            int rr = ok ? row : n - 1;
            v[k] = *(const float4*)(fcol + (size_t)rr * H);
            a[k] = ok ? g_e[rr] : 0.f;
            sg[k] = g_seg[rr];
        }
        #pragma unroll
        for (int k = 0; k < 4; k++) {
            if (sg[k] != cur) {
                float* dst = g_rst + (size_t)cur * H + cq * 4;
                atomicAdd(dst + 0, acc.x);
                atomicAdd(dst + 1, acc.y);
                atomicAdd(dst + 2, acc.z);
                atomicAdd(dst + 3, acc.w);
                acc = make_float4(0.f, 0.f, 0.f, 0.f);
                cur = sg[k];
            }
            acc.x += a[k] * v[k].x;
            acc.y += a[k] * v[k].y;
            acc.z += a[k] * v[k].z;
            acc.w += a[k] * v[k].w;
        }
    }
    float* dst = g_rst + (size_t)cur * H + cq * 4;
    atomicAdd(dst + 0, acc.x);
    atomicAdd(dst + 1, acc.y);
    atomicAdd(dst + 2, acc.z);
    atomicAdd(dst + 3, acc.w);
}

// ---------------------------------------------------------------------------
// out = rst @ Wout.T, tf32 SIMT MMA with cp.async (known good, 17us).
// ---------------------------------------------------------------------------
#define PITCH 36
#define B_ST  (256 * PITCH)
#define A_ST_O (32 * PITCH)

__global__ __launch_bounds__(256, 2) void out_gemm_mma(
    float* __restrict__ out, const float* __restrict__ Wout, int m)
{
    extern __shared__ float sm[];
    float* As  = sm;
    float* Bsm = sm + 2 * A_ST_O;

    const int tid  = threadIdx.x;
    const int lane = tid & 31;
    const int warp = tid >> 5;
    const int wm = warp >> 2;
    const int wn = warp & 3;
    const int g  = lane >> 2;
    const int t4 = lane & 3;
    const int row0 = blockIdx.x * 32;

    const uint32_t sAb = (uint32_t)__cvta_generic_to_shared(As);
    const uint32_t sBb = (uint32_t)__cvta_generic_to_shared(Bsm);

    float acc[8][4];
    #pragma unroll
    for (int ni = 0; ni < 8; ni++)
        #pragma unroll
        for (int q = 0; q < 4; q++) acc[ni][q] = 0.f;

    auto issue = [&](int buf, int k0) {
        {
            int ar = tid >> 3, kq = tid & 7;
            int grow = row0 + ar; if (grow >= m) grow = m - 1;
            cpa16(sAb + (uint32_t)(buf * A_ST_O + ar * PITCH + kq * 4) * 4u,
                  g_rst + (size_t)grow * H + k0 + kq * 4);
        }
        #pragma unroll
        for (int q = 0; q < 8; q++) {
            cpa16(sBb + (uint32_t)(buf * B_ST + tid * PITCH + q * 4) * 4u,
                  Wout + (size_t)tid * H + k0 + q * 4);
        }
        CP_COMMIT();
    };

    issue(0, 0);
    for (int s = 0; s < 8; s++) {
        if (s + 1 < 8) { issue((s + 1) & 1, (s + 1) * 32); CP_WAIT1(); }
        else           { CP_WAIT0(); }
        __syncthreads();

        const float* Ab = As  + (s & 1) * A_ST_O;
        const float* Bb = Bsm + (s & 1) * B_ST;

        #pragma unroll
        for (int ks = 0; ks < 4; ks++) {
            const int kb = ks * 8;
            const float* ab = Ab + (wm * 16) * PITCH;
            uint32_t a0 = __float_as_uint(ab[(g    ) * PITCH + kb + t4    ]);
            uint32_t a1 = __float_as_uint(ab[(g + 8) * PITCH + kb + t4    ]);
            uint32_t a2 = __float_as_uint(ab[(g    ) * PITCH + kb + t4 + 4]);
            uint32_t a3 = __float_as_uint(ab[(g + 8) * PITCH + kb + t4 + 4]);
            #pragma unroll
            for (int ni = 0; ni < 8; ni++) {
                const int nc = wn * 64 + ni * 8 + g;
                uint32_t b0 = __float_as_uint(Bb[nc * PITCH + kb + t4    ]);
                uint32_t b1 = __float_as_uint(Bb[nc * PITCH + kb + t4 + 4]);
                mma_tf32(acc[ni][0], acc[ni][1], acc[ni][2], acc[ni][3],
                         a0, a1, a2, a3, b0, b1);
            }
        }
        __syncthreads();
    }

    const int r0 = row0 + wm * 16 + g;
    const int r1 = r0 + 8;
    #pragma unroll
    for (int ni = 0; ni < 8; ni++) {
        const int c0 = wn * 64 + ni * 8 + t4 * 2;
        if (r0 < m) *(float2*)(out + (size_t)r0 * H + c0) = make_float2(acc[ni][0], acc[ni][1]);
        if (r1 < m) *(float2*)(out + (size_t)r1 * H + c0) = make_float2(acc[ni][2], acc[ni][3]);
    }
}

extern "C" void kernel_launch(void* const* d_in, const int* in_sizes, int n_in,
                              void* d_out, int out_size) {
    const float* feats = (const float*)d_in[0];
    const float* ctx   = (const float*)d_in[1];
    const void*  lens  = d_in[2];
    const float* Wu    = (const float*)d_in[3];
    const float* bu    = (const float*)d_in[4];
    const float* Wv    = (const float*)d_in[5];
    const float* We    = (const float*)d_in[6];
    const float* Wout  = (const float*)d_in[7];
    float* out = (float*)d_out;

    const int n = in_sizes[0] / H;
    const int b = out_size / H;

    const int smem_out = (2 * A_ST_O + 2 * B_ST) * 4;
    cudaFuncSetAttribute(e_gemm_f16,   cudaFuncAttributeMaxDynamicSharedMemorySize, EPS_TOT);
    cudaFuncSetAttribute(out_gemm_mma, cudaFuncAttributeMaxDynamicSharedMemorySize, smem_out);

    float* Wout_r = nullptr; cudaGetSymbolAddress((void**)&Wout_r, g_Wr);

    const int total4 = b * H / 4;
    scan_kernel<<<1, 1024>>>(lens, b, n);
    conv_w_kernel<<<256, 256>>>(Wu, Wv, Wout);
    zero_rst_kernel<<<(total4 + 1023) / 1024, 1024>>>(total4);
    e_gemm_f16<<<(n + 63) / 64, 256, EPS_TOT>>>(feats, ctx, bu, We, n);
    alpha_kernel<<<(b + 7) / 8, 256>>>(b);
    pool_flat_kernel<<<(n + 63) / 64, 256>>>(feats, n);
    out_gemm_mma<<<(b + 31) / 32, 256, smem_out>>>(out, Wout_r, b);
}

// round 16
// speedup vs baseline: 1.3634x; 1.3634x over previous
#include <cuda_runtime.h>
#include <cuda_fp16.h>
#include <cstdint>
#include <cstring>

#define H 256
#define NMAX 204800
#define BMAX 4096

__device__ float  g_e[NMAX];           // e scores, then alpha (in-place)
__device__ int    g_seg[NMAX];         // segment id per row
__device__ float  g_rst[BMAX * H];
__device__ int    g_off[BMAX + 1];
__device__ __half g_Wh[256 * 512];     // [col j][Wu row j | Wv row j]
__device__ float  g_Wr[H * H];         // tf32-RNA rounded Wout

// ---------------------------------------------------------------------------
// helpers
// ---------------------------------------------------------------------------
__device__ __forceinline__ uint32_t h2u(__half2 h) {
    uint32_t u;
    memcpy(&u, &h, 4);
    return u;
}
__device__ __forceinline__ void cpa16(uint32_t dst, const void* src) {
    asm volatile("cp.async.cg.shared.global [%0], [%1], 16;\n" :: "r"(dst), "l"(src));
}
#define CP_COMMIT() asm volatile("cp.async.commit_group;\n" ::: "memory")
#define CP_WAIT0()  asm volatile("cp.async.wait_group 0;\n" ::: "memory")
#define CP_WAIT1()  asm volatile("cp.async.wait_group 1;\n" ::: "memory")

__device__ __forceinline__ void mma_f16(float& d0, float& d1, float& d2, float& d3,
                                        uint32_t a0, uint32_t a1, uint32_t a2, uint32_t a3,
                                        uint32_t b0, uint32_t b1) {
    asm volatile("mma.sync.aligned.m16n8k16.row.col.f32.f16.f16.f32 "
                 "{%0,%1,%2,%3},{%4,%5,%6,%7},{%8,%9},{%0,%1,%2,%3};\n"
                 : "+f"(d0), "+f"(d1), "+f"(d2), "+f"(d3)
                 : "r"(a0), "r"(a1), "r"(a2), "r"(a3), "r"(b0), "r"(b1));
}
__device__ __forceinline__ void mma_tf32(float& d0, float& d1, float& d2, float& d3,
                                         uint32_t a0, uint32_t a1, uint32_t a2, uint32_t a3,
                                         uint32_t b0, uint32_t b1) {
    asm volatile("mma.sync.aligned.m16n8k8.row.col.f32.tf32.tf32.f32 "
                 "{%0,%1,%2,%3},{%4,%5,%6,%7},{%8,%9},{%0,%1,%2,%3};\n"
                 : "+f"(d0), "+f"(d1), "+f"(d2), "+f"(d3)
                 : "r"(a0), "r"(a1), "r"(a2), "r"(a3), "r"(b0), "r"(b1));
}
__device__ __forceinline__ void ldsm_x4(uint32_t& r0, uint32_t& r1, uint32_t& r2, uint32_t& r3,
                                        uint32_t addr) {
    asm volatile("ldmatrix.sync.aligned.m8n8.x4.shared.b16 {%0,%1,%2,%3}, [%4];"
                 : "=r"(r0), "=r"(r1), "=r"(r2), "=r"(r3) : "r"(addr));
}

// ---------------------------------------------------------------------------
// Prefix scan of ragged lengths (runtime int32/int64 detection).
// ---------------------------------------------------------------------------
__global__ __launch_bounds__(1024) void scan_kernel(const void* lens_raw, int b, int n_total) {
    __shared__ long long s[1024];
    __shared__ int use64;
    const int tid = threadIdx.x;
    const int* p32 = (const int*)lens_raw;

    long long local = 0;
    for (int i = tid; i < b; i += 1024) local += (long long)p32[i];
    s[tid] = local;
    __syncthreads();
    for (int o = 512; o > 0; o >>= 1) {
        if (tid < o) s[tid] += s[tid + o];
        __syncthreads();
    }
    if (tid == 0) use64 = (s[0] == (long long)n_total) ? 0 : 1;
    __syncthreads();
    const int u64 = use64;
    __syncthreads();

    const int PER = 4;
    long long v[PER];
    long long loc = 0;
    #pragma unroll
    for (int q = 0; q < PER; q++) {
        int i = tid * PER + q;
        long long val = 0;
        if (i < b) val = u64 ? ((const long long*)lens_raw)[i] : (long long)p32[i];
        v[q] = val;
        loc += val;
    }
    s[tid] = loc;
    __syncthreads();
    for (int o = 1; o < 1024; o <<= 1) {
        long long t = (tid >= o) ? s[tid - o] : 0;
        __syncthreads();
        s[tid] += t;
        __syncthreads();
    }
    long long run = s[tid] - loc;
    #pragma unroll
    for (int q = 0; q < PER; q++) {
        int i = tid * PER + q;
        if (i < b) {
            g_off[i] = (int)run;
            run += v[q];
            if (i == b - 1) g_off[b] = (int)run;
        }
    }
}

// ---------------------------------------------------------------------------
// Weight prep: fp16 [Wu|Wv] K-major per output col; tf32-RNA Wout.
// ---------------------------------------------------------------------------
__global__ __launch_bounds__(256) void conv_w_kernel(
    const float* __restrict__ Wu, const float* __restrict__ Wv, const float* __restrict__ Wout)
{
    const int j = blockIdx.x, k = threadIdx.x;
    g_Wh[j * 512 + k]       = __float2half_rn(Wu[j * H + k]);
    g_Wh[j * 512 + 256 + k] = __float2half_rn(Wv[j * H + k]);
    uint32_t c;
    asm("cvt.rna.tf32.f32 %0, %1;" : "=r"(c) : "f"(Wout[j * H + k]));
    g_Wr[j * H + k] = __uint_as_float(c);
}

// ---------------------------------------------------------------------------
// Fused e-GEMM, fp16 m16n8k16, LDSM fragments, fp32 A loaded+converted inline.
// BM=128, BN=256, K=512, BK=32. 512 threads, 16 warps 4x4; warp tile 32x64.
// A double-buffered (reg prefetch), B 3-stage cp.async ring.
// Wait math: pending at iter s = {B(s), B(s+1)}; WAIT1 completes exactly B(s).
// issueB(s+2) after the barrier: readers of buffer (s+2)%3 (= stage s-1)
// all passed the barrier -> no write/read race.
// ---------------------------------------------------------------------------
#define EPS_B   20480
#define EPS_BU  81920
#define EPS_WE  82944
#define EPS_ER  83968
#define EPS_TOT 86016

__global__ __launch_bounds__(512, 1) void e_gemm_f16(
    const float* __restrict__ feats, const float* __restrict__ ctx,
    const float* __restrict__ bu, const float* __restrict__ We, int n)
{
    extern __shared__ char smc[];
    const uint32_t smb = (uint32_t)__cvta_generic_to_shared(smc);
    float* sbu  = (float*)(smc + EPS_BU);
    float* sWe  = (float*)(smc + EPS_WE);
    float* ered = (float*)(smc + EPS_ER);   // [128][4]

    const int tid  = threadIdx.x;
    const int lane = tid & 31;
    const int warp = tid >> 5;
    const int wm = warp >> 2;     // 0..3
    const int wn = warp & 3;      // 0..3
    const int g  = lane >> 2;
    const int t4 = lane & 3;
    const int row0 = blockIdx.x * 128;

    const int ar = tid >> 2;
    const int ac = tid & 3;
    int arow = row0 + ar; if (arow >= n) arow = n - 1;

    float acc[2][8][4];
    #pragma unroll
    for (int mi = 0; mi < 2; mi++)
        #pragma unroll
        for (int ni = 0; ni < 8; ni++)
            #pragma unroll
            for (int q = 0; q < 4; q++) acc[mi][ni][q] = 0.f;

    float4 avA, avB;

    auto ldgA = [&](int sidx) {
        const int k0 = sidx * 32;
        const float* Ap = (k0 < 256) ? feats : ctx;
        const float* p = Ap + (size_t)arow * H + (k0 & 255) + ac * 8;
        avA = *(const float4*)p;
        avB = *(const float4*)(p + 4);
    };
    auto stsA = [&](int buf) {
        uint4 u;
        u.x = h2u(__floats2half2_rn(avA.x, avA.y));
        u.y = h2u(__floats2half2_rn(avA.z, avA.w));
        u.z = h2u(__floats2half2_rn(avB.x, avB.y));
        u.w = h2u(__floats2half2_rn(avB.z, avB.w));
        *(uint4*)(smc + buf * 10240 + ar * 80 + ac * 16) = u;
    };
    auto issueB = [&](int buf, int sidx) {
        const int k0 = sidx * 32;
        #pragma unroll
        for (int q = 0; q < 2; q++) {
            int idx = tid + q * 512;
            int j = idx >> 2, c = idx & 3;
            cpa16(smb + (uint32_t)(EPS_B + buf * 20480 + j * 80 + c * 16),
                  g_Wh + (size_t)j * 512 + k0 + c * 8);
        }
        CP_COMMIT();
    };

    const int a_row_in = (lane & 15);
    const int a_koff   = (lane >> 4) * 8;
    const int b_col_in = ((lane >> 4) & 1) * 8 + (lane & 7);
    const int b_koff   = ((lane >> 3) & 1) * 8;

    ldgA(0); stsA(0);
    issueB(0, 0);
    issueB(1, 1);
    if (tid < 256) { sbu[tid] = bu[tid]; sWe[tid] = We[tid]; }

    for (int s = 0; s < 16; s++) {
        if (s + 1 < 16) { ldgA(s + 1); CP_WAIT1(); }   // completes B(s)
        else            { CP_WAIT0(); }
        __syncthreads();                                // all warps done with stage s-1
        if (s + 2 < 16) issueB((s + 2) % 3, s + 2);     // safe: old readers finished

        const uint32_t abase = smb + (s & 1) * 10240;
        const uint32_t bbase = smb + EPS_B + (s % 3) * 20480;

        #pragma unroll
        for (int kc = 0; kc < 2; kc++) {
            const int kw = kc * 16;
            uint32_t af[2][4];
            #pragma unroll
            for (int mi = 0; mi < 2; mi++) {
                ldsm_x4(af[mi][0], af[mi][1], af[mi][2], af[mi][3],
                        abase + (uint32_t)((wm * 32 + mi * 16 + a_row_in) * 80
                                           + (kw + a_koff) * 2));
            }
            uint32_t bf[8][2];
            #pragma unroll
            for (int n2 = 0; n2 < 4; n2++) {
                ldsm_x4(bf[n2 * 2][0], bf[n2 * 2][1], bf[n2 * 2 + 1][0], bf[n2 * 2 + 1][1],
                        bbase + (uint32_t)((wn * 64 + n2 * 16 + b_col_in) * 80
                                           + (kw + b_koff) * 2));
            }
            #pragma unroll
            for (int mi = 0; mi < 2; mi++)
                #pragma unroll
                for (int ni = 0; ni < 8; ni++)
                    mma_f16(acc[mi][ni][0], acc[mi][ni][1], acc[mi][ni][2], acc[mi][ni][3],
                            af[mi][0], af[mi][1], af[mi][2], af[mi][3],
                            bf[ni][0], bf[ni][1]);
        }
        if (s + 1 < 16) stsA((s + 1) & 1);
    }

    // Epilogue: sigmoid(h+bu)·We, row partials across wn
    float part[4] = {0.f, 0.f, 0.f, 0.f};
    #pragma unroll
    for (int mi = 0; mi < 2; mi++) {
        #pragma unroll
        for (int ni = 0; ni < 8; ni++) {
            const int c0 = wn * 64 + ni * 8 + t4 * 2;
            const int c1 = c0 + 1;
            const float w0 = sWe[c0], w1 = sWe[c1];
            const float b0 = sbu[c0], b1 = sbu[c1];
            float x;
            x = acc[mi][ni][0] + b0; part[mi * 2 + 0] += w0 / (1.f + __expf(-x));
            x = acc[mi][ni][1] + b1; part[mi * 2 + 0] += w1 / (1.f + __expf(-x));
            x = acc[mi][ni][2] + b0; part[mi * 2 + 1] += w0 / (1.f + __expf(-x));
            x = acc[mi][ni][3] + b1; part[mi * 2 + 1] += w1 / (1.f + __expf(-x));
        }
    }
    #pragma unroll
    for (int o = 1; o <= 2; o <<= 1)
        #pragma unroll
        for (int p = 0; p < 4; p++)
            part[p] += __shfl_xor_sync(0xffffffffu, part[p], o);
    if (t4 == 0) {
        #pragma unroll
        for (int p = 0; p < 4; p++) {
            int rl = wm * 32 + (p >> 1) * 16 + (p & 1) * 8 + g;
            ered[rl * 4 + wn] = part[p];
        }
    }
    __syncthreads();
    if (tid < 128) {
        int row = row0 + tid;
        if (row < n)
            g_e[row] = ered[tid * 4 + 0] + ered[tid * 4 + 1] + ered[tid * 4 + 2] + ered[tid * 4 + 3];
    }
}

// ---------------------------------------------------------------------------
// Zero g_rst (atomic accumulation target).
// ---------------------------------------------------------------------------
__global__ __launch_bounds__(1024) void zero_rst_kernel(int total4) {
    int i = blockIdx.x * 1024 + threadIdx.x;
    if (i < total4) ((float4*)g_rst)[i] = make_float4(0.f, 0.f, 0.f, 0.f);
}

// ---------------------------------------------------------------------------
// One WARP per segment: softmax over g_e in place (alpha), write seg ids.
// ---------------------------------------------------------------------------
__global__ __launch_bounds__(256) void alpha_kernel(int b) {
    const int seg = blockIdx.x * 8 + (threadIdx.x >> 5);
    if (seg >= b) return;
    const int lane = threadIdx.x & 31;
    const int base = g_off[seg];
    const int len  = g_off[seg + 1] - base;
    if (len <= 0) return;

    float m = -1e30f;
    for (int i = lane; i < len; i += 32) m = fmaxf(m, g_e[base + i]);
    #pragma unroll
    for (int o = 16; o > 0; o >>= 1) m = fmaxf(m, __shfl_xor_sync(0xffffffffu, m, o));

    float d = 0.f;
    for (int i = lane; i < len; i += 32) d += __expf(g_e[base + i] - m);
    #pragma unroll
    for (int o = 16; o > 0; o >>= 1) d += __shfl_xor_sync(0xffffffffu, d, o);
    const float inv = 1.f / d;

    for (int i = lane; i < len; i += 32) {
        g_e[base + i] = __expf(g_e[base + i] - m) * inv;
        g_seg[base + i] = seg;
    }
}

// ---------------------------------------------------------------------------
// Flat weighted pooling: 64 global rows per block, streaming, atomic flush
// at segment boundaries. thread = (row-group r4, column quad cq).
// ---------------------------------------------------------------------------
__global__ __launch_bounds__(256) void pool_flat_kernel(const float* __restrict__ feats, int n) {
    const int tid = threadIdx.x;
    const int r4 = tid >> 6;        // 0..3
    const int cq = tid & 63;        // 0..63
    const int row0 = blockIdx.x * 64 + r4;
    if (row0 >= n) return;
    const float* fcol = feats + cq * 4;

    int cur = g_seg[row0];
    float4 acc = make_float4(0.f, 0.f, 0.f, 0.f);

    #pragma unroll
    for (int j0 = 0; j0 < 16; j0 += 4) {
        float4 v[4]; float a[4]; int sg[4];
        #pragma unroll
        for (int k = 0; k < 4; k++) {
            int row = row0 + (j0 + k) * 4;
            bool ok = row < n;
            int rr = ok ? row : n - 1;
            v[k] = *(const float4*)(fcol + (size_t)rr * H);
            a[k] = ok ? g_e[rr] : 0.f;
            sg[k] = g_seg[rr];
        }
        #pragma unroll
        for (int k = 0; k < 4; k++) {
            if (sg[k] != cur) {
                float* dst = g_rst + (size_t)cur * H + cq * 4;
                atomicAdd(dst + 0, acc.x);
                atomicAdd(dst + 1, acc.y);
                atomicAdd(dst + 2, acc.z);
                atomicAdd(dst + 3, acc.w);
                acc = make_float4(0.f, 0.f, 0.f, 0.f);
                cur = sg[k];
            }
            acc.x += a[k] * v[k].x;
            acc.y += a[k] * v[k].y;
            acc.z += a[k] * v[k].z;
            acc.w += a[k] * v[k].w;
        }
    }
    float* dst = g_rst + (size_t)cur * H + cq * 4;
    atomicAdd(dst + 0, acc.x);
    atomicAdd(dst + 1, acc.y);
    atomicAdd(dst + 2, acc.z);
    atomicAdd(dst + 3, acc.w);
}

// ---------------------------------------------------------------------------
// out = rst @ Wout.T, tf32 SIMT MMA with cp.async.
// issue(s+1) after barrier -> exactly ONE group in flight at each wait, so
// the wait must be WAIT0 (WAIT1 would be a silent no-op => garbage reads).
// ---------------------------------------------------------------------------
#define PITCH 36
#define B_ST  (256 * PITCH)
#define A_ST_O (32 * PITCH)

__global__ __launch_bounds__(256, 2) void out_gemm_mma(
    float* __restrict__ out, const float* __restrict__ Wout, int m)
{
    extern __shared__ float sm[];
    float* As  = sm;
    float* Bsm = sm + 2 * A_ST_O;

    const int tid  = threadIdx.x;
    const int lane = tid & 31;
    const int warp = tid >> 5;
    const int wm = warp >> 2;
    const int wn = warp & 3;
    const int g  = lane >> 2;
    const int t4 = lane & 3;
    const int row0 = blockIdx.x * 32;

    const uint32_t sAb = (uint32_t)__cvta_generic_to_shared(As);
    const uint32_t sBb = (uint32_t)__cvta_generic_to_shared(Bsm);

    float acc[8][4];
    #pragma unroll
    for (int ni = 0; ni < 8; ni++)
        #pragma unroll
        for (int q = 0; q < 4; q++) acc[ni][q] = 0.f;

    auto issue = [&](int buf, int k0) {
        {
            int ar = tid >> 3, kq = tid & 7;
            int grow = row0 + ar; if (grow >= m) grow = m - 1;
            cpa16(sAb + (uint32_t)(buf * A_ST_O + ar * PITCH + kq * 4) * 4u,
                  g_rst + (size_t)grow * H + k0 + kq * 4);
        }
        #pragma unroll
        for (int q = 0; q < 8; q++) {
            cpa16(sBb + (uint32_t)(buf * B_ST + tid * PITCH + q * 4) * 4u,
                  Wout + (size_t)tid * H + k0 + q * 4);
        }
        CP_COMMIT();
    };

    issue(0, 0);
    for (int s = 0; s < 8; s++) {
        CP_WAIT0();                    // single group in flight: must be WAIT0
        __syncthreads();
        if (s + 1 < 8) issue((s + 1) & 1, (s + 1) * 32);   // after barrier: safe

        const float* Ab = As  + (s & 1) * A_ST_O;
        const float* Bb = Bsm + (s & 1) * B_ST;

        #pragma unroll
        for (int ks = 0; ks < 4; ks++) {
            const int kb = ks * 8;
            const float* ab = Ab + (wm * 16) * PITCH;
            uint32_t a0 = __float_as_uint(ab[(g    ) * PITCH + kb + t4    ]);
            uint32_t a1 = __float_as_uint(ab[(g + 8) * PITCH + kb + t4    ]);
            uint32_t a2 = __float_as_uint(ab[(g    ) * PITCH + kb + t4 + 4]);
            uint32_t a3 = __float_as_uint(ab[(g + 8) * PITCH + kb + t4 + 4]);
            #pragma unroll
            for (int ni = 0; ni < 8; ni++) {
                const int nc = wn * 64 + ni * 8 + g;
                uint32_t b0 = __float_as_uint(Bb[nc * PITCH + kb + t4    ]);
                uint32_t b1 = __float_as_uint(Bb[nc * PITCH + kb + t4 + 4]);
                mma_tf32(acc[ni][0], acc[ni][1], acc[ni][2], acc[ni][3],
                         a0, a1, a2, a3, b0, b1);
            }
        }
    }

    const int r0 = row0 + wm * 16 + g;
    const int r1 = r0 + 8;
    #pragma unroll
    for (int ni = 0; ni < 8; ni++) {
        const int c0 = wn * 64 + ni * 8 + t4 * 2;
        if (r0 < m) *(float2*)(out + (size_t)r0 * H + c0) = make_float2(acc[ni][0], acc[ni][1]);
        if (r1 < m) *(float2*)(out + (size_t)r1 * H + c0) = make_float2(acc[ni][2], acc[ni][3]);
    }
}

extern "C" void kernel_launch(void* const* d_in, const int* in_sizes, int n_in,
                              void* d_out, int out_size) {
    const float* feats = (const float*)d_in[0];
    const float* ctx   = (const float*)d_in[1];
    const void*  lens  = d_in[2];
    const float* Wu    = (const float*)d_in[3];
    const float* bu    = (const float*)d_in[4];
    const float* Wv    = (const float*)d_in[5];
    const float* We    = (const float*)d_in[6];
    const float* Wout  = (const float*)d_in[7];
    float* out = (float*)d_out;

    const int n = in_sizes[0] / H;
    const int b = out_size / H;

    const int smem_out = (2 * A_ST_O + 2 * B_ST) * 4;
    cudaFuncSetAttribute(e_gemm_f16,   cudaFuncAttributeMaxDynamicSharedMemorySize, EPS_TOT);
    cudaFuncSetAttribute(out_gemm_mma, cudaFuncAttributeMaxDynamicSharedMemorySize, smem_out);

    float* Wout_r = nullptr; cudaGetSymbolAddress((void**)&Wout_r, g_Wr);

    const int total4 = b * H / 4;
    scan_kernel<<<1, 1024>>>(lens, b, n);
    conv_w_kernel<<<256, 256>>>(Wu, Wv, Wout);
    zero_rst_kernel<<<(total4 + 1023) / 1024, 1024>>>(total4);
    e_gemm_f16<<<(n + 127) / 128, 512, EPS_TOT>>>(feats, ctx, bu, We, n);
    alpha_kernel<<<(b + 7) / 8, 256>>>(b);
    pool_flat_kernel<<<(n + 63) / 64, 256>>>(feats, n);
    out_gemm_mma<<<(b + 31) / 32, 256, smem_out>>>(out, Wout_r, b);
}

// round 17
// speedup vs baseline: 1.4135x; 1.0368x over previous
#include <cuda_runtime.h>
#include <cuda_fp16.h>
#include <cstdint>
#include <cstring>

#define H 256
#define NMAX 204800
#define BMAX 4096

__device__ float  g_e[NMAX];           // e scores, then alpha (in-place)
__device__ int    g_seg[NMAX];         // segment id per row
__device__ float  g_rst[BMAX * H];
__device__ int    g_off[BMAX + 1];
__device__ __half g_Wh[256 * 512];     // [col j][Wu row j | Wv row j]
__device__ float  g_Wr[H * H];         // tf32-RNA rounded Wout

// ---------------------------------------------------------------------------
// helpers
// ---------------------------------------------------------------------------
__device__ __forceinline__ uint32_t h2u(__half2 h) {
    uint32_t u;
    memcpy(&u, &h, 4);
    return u;
}
__device__ __forceinline__ void cpa16(uint32_t dst, const void* src) {
    asm volatile("cp.async.cg.shared.global [%0], [%1], 16;\n" :: "r"(dst), "l"(src));
}
#define CP_COMMIT() asm volatile("cp.async.commit_group;\n" ::: "memory")
#define CP_WAIT0()  asm volatile("cp.async.wait_group 0;\n" ::: "memory")
#define CP_WAIT1()  asm volatile("cp.async.wait_group 1;\n" ::: "memory")
#define CP_WAIT2()  asm volatile("cp.async.wait_group 2;\n" ::: "memory")

__device__ __forceinline__ void mma_f16(float& d0, float& d1, float& d2, float& d3,
                                        uint32_t a0, uint32_t a1, uint32_t a2, uint32_t a3,
                                        uint32_t b0, uint32_t b1) {
    asm volatile("mma.sync.aligned.m16n8k16.row.col.f32.f16.f16.f32 "
                 "{%0,%1,%2,%3},{%4,%5,%6,%7},{%8,%9},{%0,%1,%2,%3};\n"
                 : "+f"(d0), "+f"(d1), "+f"(d2), "+f"(d3)
                 : "r"(a0), "r"(a1), "r"(a2), "r"(a3), "r"(b0), "r"(b1));
}
__device__ __forceinline__ void mma_tf32(float& d0, float& d1, float& d2, float& d3,
                                         uint32_t a0, uint32_t a1, uint32_t a2, uint32_t a3,
                                         uint32_t b0, uint32_t b1) {
    asm volatile("mma.sync.aligned.m16n8k8.row.col.f32.tf32.tf32.f32 "
                 "{%0,%1,%2,%3},{%4,%5,%6,%7},{%8,%9},{%0,%1,%2,%3};\n"
                 : "+f"(d0), "+f"(d1), "+f"(d2), "+f"(d3)
                 : "r"(a0), "r"(a1), "r"(a2), "r"(a3), "r"(b0), "r"(b1));
}
__device__ __forceinline__ void ldsm_x4(uint32_t& r0, uint32_t& r1, uint32_t& r2, uint32_t& r3,
                                        uint32_t addr) {
    asm volatile("ldmatrix.sync.aligned.m8n8.x4.shared.b16 {%0,%1,%2,%3}, [%4];"
                 : "=r"(r0), "=r"(r1), "=r"(r2), "=r"(r3) : "r"(addr));
}

// ---------------------------------------------------------------------------
// Prefix scan of ragged lengths (runtime int32/int64 detection).
// ---------------------------------------------------------------------------
__global__ __launch_bounds__(1024) void scan_kernel(const void* lens_raw, int b, int n_total) {
    __shared__ long long s[1024];
    __shared__ int use64;
    const int tid = threadIdx.x;
    const int* p32 = (const int*)lens_raw;

    long long local = 0;
    for (int i = tid; i < b; i += 1024) local += (long long)p32[i];
    s[tid] = local;
    __syncthreads();
    for (int o = 512; o > 0; o >>= 1) {
        if (tid < o) s[tid] += s[tid + o];
        __syncthreads();
    }
    if (tid == 0) use64 = (s[0] == (long long)n_total) ? 0 : 1;
    __syncthreads();
    const int u64 = use64;
    __syncthreads();

    const int PER = 4;
    long long v[PER];
    long long loc = 0;
    #pragma unroll
    for (int q = 0; q < PER; q++) {
        int i = tid * PER + q;
        long long val = 0;
        if (i < b) val = u64 ? ((const long long*)lens_raw)[i] : (long long)p32[i];
        v[q] = val;
        loc += val;
    }
    s[tid] = loc;
    __syncthreads();
    for (int o = 1; o < 1024; o <<= 1) {
        long long t = (tid >= o) ? s[tid - o] : 0;
        __syncthreads();
        s[tid] += t;
        __syncthreads();
    }
    long long run = s[tid] - loc;
    #pragma unroll
    for (int q = 0; q < PER; q++) {
        int i = tid * PER + q;
        if (i < b) {
            g_off[i] = (int)run;
            run += v[q];
            if (i == b - 1) g_off[b] = (int)run;
        }
    }
}

// ---------------------------------------------------------------------------
// Weight prep: fp16 [Wu|Wv] K-major per output col; tf32-RNA Wout.
// ---------------------------------------------------------------------------
__global__ __launch_bounds__(256) void conv_w_kernel(
    const float* __restrict__ Wu, const float* __restrict__ Wv, const float* __restrict__ Wout)
{
    const int j = blockIdx.x, k = threadIdx.x;
    g_Wh[j * 512 + k]       = __float2half_rn(Wu[j * H + k]);
    g_Wh[j * 512 + 256 + k] = __float2half_rn(Wv[j * H + k]);
    uint32_t c;
    asm("cvt.rna.tf32.f32 %0, %1;" : "=r"(c) : "f"(Wout[j * H + k]));
    g_Wr[j * H + k] = __uint_as_float(c);
}

// ---------------------------------------------------------------------------
// Fused e-GEMM, fp16 m16n8k16, LDSM fragments, fp32 A loaded+converted inline.
// BM=128, BN=256, K=512, BK=32. 512 threads, 16 warps 4x4; warp tile 32x64.
// A double-buffered (reg prefetch). B: 4-buffer ring, 3 groups in flight,
// issue stage s+2 at TOP of iter s (k=2 <= D-2=2): the written buffer's
// previous reader is stage s-2, done by all warps (they passed BAR(s-1)).
// Pending at wait = {B(s),B(s+1),B(s+2)} -> WAIT2 completes B(s).
// SMEM: A 2x10240 @0 | B 4x20480 @20480 | sbu @102400 | sWe @103424 |
//       ered @104448 | total 106496.
// ---------------------------------------------------------------------------
#define EPS_B   20480
#define EPS_BU  102400
#define EPS_WE  103424
#define EPS_ER  104448
#define EPS_TOT 106496

__global__ __launch_bounds__(512, 1) void e_gemm_f16(
    const float* __restrict__ feats, const float* __restrict__ ctx,
    const float* __restrict__ bu, const float* __restrict__ We, int n)
{
    extern __shared__ char smc[];
    const uint32_t smb = (uint32_t)__cvta_generic_to_shared(smc);
    float* sbu  = (float*)(smc + EPS_BU);
    float* sWe  = (float*)(smc + EPS_WE);
    float* ered = (float*)(smc + EPS_ER);   // [128][4]

    const int tid  = threadIdx.x;
    const int lane = tid & 31;
    const int warp = tid >> 5;
    const int wm = warp >> 2;     // 0..3
    const int wn = warp & 3;      // 0..3
    const int g  = lane >> 2;
    const int t4 = lane & 3;
    const int row0 = blockIdx.x * 128;

    const int ar = tid >> 2;
    const int ac = tid & 3;
    int arow = row0 + ar; if (arow >= n) arow = n - 1;

    float acc[2][8][4];
    #pragma unroll
    for (int mi = 0; mi < 2; mi++)
        #pragma unroll
        for (int ni = 0; ni < 8; ni++)
            #pragma unroll
            for (int q = 0; q < 4; q++) acc[mi][ni][q] = 0.f;

    float4 avA, avB;

    auto ldgA = [&](int sidx) {
        const int k0 = sidx * 32;
        const float* Ap = (k0 < 256) ? feats : ctx;
        const float* p = Ap + (size_t)arow * H + (k0 & 255) + ac * 8;
        avA = *(const float4*)p;
        avB = *(const float4*)(p + 4);
    };
    auto stsA = [&](int buf) {
        uint4 u;
        u.x = h2u(__floats2half2_rn(avA.x, avA.y));
        u.y = h2u(__floats2half2_rn(avA.z, avA.w));
        u.z = h2u(__floats2half2_rn(avB.x, avB.y));
        u.w = h2u(__floats2half2_rn(avB.z, avB.w));
        *(uint4*)(smc + buf * 10240 + ar * 80 + ac * 16) = u;
    };
    auto issueB = [&](int buf, int sidx) {
        const int k0 = sidx * 32;
        #pragma unroll
        for (int q = 0; q < 2; q++) {
            int idx = tid + q * 512;
            int j = idx >> 2, c = idx & 3;
            cpa16(smb + (uint32_t)(EPS_B + buf * 20480 + j * 80 + c * 16),
                  g_Wh + (size_t)j * 512 + k0 + c * 8);
        }
        CP_COMMIT();
    };

    const int a_row_in = (lane & 15);
    const int a_koff   = (lane >> 4) * 8;
    const int b_col_in = ((lane >> 4) & 1) * 8 + (lane & 7);
    const int b_koff   = ((lane >> 3) & 1) * 8;

    ldgA(0); stsA(0);
    issueB(0, 0);
    issueB(1, 1);
    if (tid < 256) { sbu[tid] = bu[tid]; sWe[tid] = We[tid]; }

    for (int s = 0; s < 16; s++) {
        if (s + 1 < 16) ldgA(s + 1);
        // issue BEFORE wait: buffer (s+2)%4's previous reader is stage s-2,
        // finished by all warps (they passed BAR(s-1)) -> race-free.
        if (s + 2 < 16)      { issueB((s + 2) & 3, s + 2); CP_WAIT2(); }
        else if (s + 1 < 16) { CP_WAIT1(); }
        else                 { CP_WAIT0(); }
        __syncthreads();

        const uint32_t abase = smb + (s & 1) * 10240;
        const uint32_t bbase = smb + EPS_B + (s & 3) * 20480;

        #pragma unroll
        for (int kc = 0; kc < 2; kc++) {
            const int kw = kc * 16;
            uint32_t af[2][4];
            #pragma unroll
            for (int mi = 0; mi < 2; mi++) {
                ldsm_x4(af[mi][0], af[mi][1], af[mi][2], af[mi][3],
                        abase + (uint32_t)((wm * 32 + mi * 16 + a_row_in) * 80
                                           + (kw + a_koff) * 2));
            }
            uint32_t bf[8][2];
            #pragma unroll
            for (int n2 = 0; n2 < 4; n2++) {
                ldsm_x4(bf[n2 * 2][0], bf[n2 * 2][1], bf[n2 * 2 + 1][0], bf[n2 * 2 + 1][1],
                        bbase + (uint32_t)((wn * 64 + n2 * 16 + b_col_in) * 80
                                           + (kw + b_koff) * 2));
            }
            #pragma unroll
            for (int mi = 0; mi < 2; mi++)
                #pragma unroll
                for (int ni = 0; ni < 8; ni++)
                    mma_f16(acc[mi][ni][0], acc[mi][ni][1], acc[mi][ni][2], acc[mi][ni][3],
                            af[mi][0], af[mi][1], af[mi][2], af[mi][3],
                            bf[ni][0], bf[ni][1]);
        }
        // A-buf (s+1)&1 was read by stage s-1; all warps passed BAR(s) -> safe.
        if (s + 1 < 16) stsA((s + 1) & 1);
    }

    // Epilogue: sigmoid(h+bu)·We, row partials across wn
    float part[4] = {0.f, 0.f, 0.f, 0.f};
    #pragma unroll
    for (int mi = 0; mi < 2; mi++) {
        #pragma unroll
        for (int ni = 0; ni < 8; ni++) {
            const int c0 = wn * 64 + ni * 8 + t4 * 2;
            const int c1 = c0 + 1;
            const float w0 = sWe[c0], w1 = sWe[c1];
            const float b0 = sbu[c0], b1 = sbu[c1];
            float x;
            x = acc[mi][ni][0] + b0; part[mi * 2 + 0] += w0 / (1.f + __expf(-x));
            x = acc[mi][ni][1] + b1; part[mi * 2 + 0] += w1 / (1.f + __expf(-x));
            x = acc[mi][ni][2] + b0; part[mi * 2 + 1] += w0 / (1.f + __expf(-x));
            x = acc[mi][ni][3] + b1; part[mi * 2 + 1] += w1 / (1.f + __expf(-x));
        }
    }
    #pragma unroll
    for (int o = 1; o <= 2; o <<= 1)
        #pragma unroll
        for (int p = 0; p < 4; p++)
            part[p] += __shfl_xor_sync(0xffffffffu, part[p], o);
    if (t4 == 0) {
        #pragma unroll
        for (int p = 0; p < 4; p++) {
            int rl = wm * 32 + (p >> 1) * 16 + (p & 1) * 8 + g;
            ered[rl * 4 + wn] = part[p];
        }
    }
    __syncthreads();
    if (tid < 128) {
        int row = row0 + tid;
        if (row < n)
            g_e[row] = ered[tid * 4 + 0] + ered[tid * 4 + 1] + ered[tid * 4 + 2] + ered[tid * 4 + 3];
    }
}

// ---------------------------------------------------------------------------
// Zero g_rst (atomic accumulation target).
// ---------------------------------------------------------------------------
__global__ __launch_bounds__(1024) void zero_rst_kernel(int total4) {
    int i = blockIdx.x * 1024 + threadIdx.x;
    if (i < total4) ((float4*)g_rst)[i] = make_float4(0.f, 0.f, 0.f, 0.f);
}

// ---------------------------------------------------------------------------
// One WARP per segment: softmax over g_e in place (alpha), write seg ids.
// ---------------------------------------------------------------------------
__global__ __launch_bounds__(256) void alpha_kernel(int b) {
    const int seg = blockIdx.x * 8 + (threadIdx.x >> 5);
    if (seg >= b) return;
    const int lane = threadIdx.x & 31;
    const int base = g_off[seg];
    const int len  = g_off[seg + 1] - base;
    if (len <= 0) return;

    float m = -1e30f;
    for (int i = lane; i < len; i += 32) m = fmaxf(m, g_e[base + i]);
    #pragma unroll
    for (int o = 16; o > 0; o >>= 1) m = fmaxf(m, __shfl_xor_sync(0xffffffffu, m, o));

    float d = 0.f;
    for (int i = lane; i < len; i += 32) d += __expf(g_e[base + i] - m);
    #pragma unroll
    for (int o = 16; o > 0; o >>= 1) d += __shfl_xor_sync(0xffffffffu, d, o);
    const float inv = 1.f / d;

    for (int i = lane; i < len; i += 32) {
        g_e[base + i] = __expf(g_e[base + i] - m) * inv;
        g_seg[base + i] = seg;
    }
}

// ---------------------------------------------------------------------------
// Flat weighted pooling: 64 global rows per block, streaming, atomic flush
// at segment boundaries. thread = (row-group r4, column quad cq).
// ---------------------------------------------------------------------------
__global__ __launch_bounds__(256) void pool_flat_kernel(const float* __restrict__ feats, int n) {
    const int tid = threadIdx.x;
    const int r4 = tid >> 6;        // 0..3
    const int cq = tid & 63;        // 0..63
    const int row0 = blockIdx.x * 64 + r4;
    if (row0 >= n) return;
    const float* fcol = feats + cq * 4;

    int cur = g_seg[row0];
    float4 acc = make_float4(0.f, 0.f, 0.f, 0.f);

    #pragma unroll
    for (int j0 = 0; j0 < 16; j0 += 4) {
        float4 v[4]; float a[4]; int sg[4];
        #pragma unroll
        for (int k = 0; k < 4; k++) {
            int row = row0 + (j0 + k) * 4;
            bool ok = row < n;
            int rr = ok ? row : n - 1;
            v[k] = *(const float4*)(fcol + (size_t)rr * H);
            a[k] = ok ? g_e[rr] : 0.f;
            sg[k] = g_seg[rr];
        }
        #pragma unroll
        for (int k = 0; k < 4; k++) {
            if (sg[k] != cur) {
                float* dst = g_rst + (size_t)cur * H + cq * 4;
                atomicAdd(dst + 0, acc.x);
                atomicAdd(dst + 1, acc.y);
                atomicAdd(dst + 2, acc.z);
                atomicAdd(dst + 3, acc.w);
                acc = make_float4(0.f, 0.f, 0.f, 0.f);
                cur = sg[k];
            }
            acc.x += a[k] * v[k].x;
            acc.y += a[k] * v[k].y;
            acc.z += a[k] * v[k].z;
            acc.w += a[k] * v[k].w;
        }
    }
    float* dst = g_rst + (size_t)cur * H + cq * 4;
    atomicAdd(dst + 0, acc.x);
    atomicAdd(dst + 1, acc.y);
    atomicAdd(dst + 2, acc.z);
    atomicAdd(dst + 3, acc.w);
}

// ---------------------------------------------------------------------------
// out = rst @ Wout.T, tf32 SIMT MMA. 3-buffer ring, issue stage s+1 at top
// of iter s (k=1 <= D-2=1): written buffer's previous reader is stage s-2,
// done by all warps. Pending = {B(s), B(s+1)} -> WAIT1 completes B(s).
// Grid = 128 blocks < 148 SMs: 1 CTA/SM occupancy is free.
// ---------------------------------------------------------------------------
#define PITCH 36
#define B_ST  (256 * PITCH)
#define A_ST_O (32 * PITCH)

__global__ __launch_bounds__(256, 1) void out_gemm_mma(
    float* __restrict__ out, const float* __restrict__ Wout, int m)
{
    extern __shared__ float sm[];
    float* As  = sm;                  // [3][A_ST_O]
    float* Bsm = sm + 3 * A_ST_O;     // [3][B_ST]

    const int tid  = threadIdx.x;
    const int lane = tid & 31;
    const int warp = tid >> 5;
    const int wm = warp >> 2;
    const int wn = warp & 3;
    const int g  = lane >> 2;
    const int t4 = lane & 3;
    const int row0 = blockIdx.x * 32;

    const uint32_t sAb = (uint32_t)__cvta_generic_to_shared(As);
    const uint32_t sBb = (uint32_t)__cvta_generic_to_shared(Bsm);

    float acc[8][4];
    #pragma unroll
    for (int ni = 0; ni < 8; ni++)
        #pragma unroll
        for (int q = 0; q < 4; q++) acc[ni][q] = 0.f;

    auto issue = [&](int buf, int k0) {
        {
            int ar = tid >> 3, kq = tid & 7;
            int grow = row0 + ar; if (grow >= m) grow = m - 1;
            cpa16(sAb + (uint32_t)(buf * A_ST_O + ar * PITCH + kq * 4) * 4u,
                  g_rst + (size_t)grow * H + k0 + kq * 4);
        }
        #pragma unroll
        for (int q = 0; q < 8; q++) {
            cpa16(sBb + (uint32_t)(buf * B_ST + tid * PITCH + q * 4) * 4u,
                  Wout + (size_t)tid * H + k0 + q * 4);
        }
        CP_COMMIT();
    };

    issue(0, 0);
    for (int s = 0; s < 8; s++) {
        if (s + 1 < 8) { issue((s + 1) % 3, (s + 1) * 32); CP_WAIT1(); }
        else           { CP_WAIT0(); }
        __syncthreads();

        const float* Ab = As  + (s % 3) * A_ST_O;
        const float* Bb = Bsm + (s % 3) * B_ST;

        #pragma unroll
        for (int ks = 0; ks < 4; ks++) {
            const int kb = ks * 8;
            const float* ab = Ab + (wm * 16) * PITCH;
            uint32_t a0 = __float_as_uint(ab[(g    ) * PITCH + kb + t4    ]);
            uint32_t a1 = __float_as_uint(ab[(g + 8) * PITCH + kb + t4    ]);
            uint32_t a2 = __float_as_uint(ab[(g    ) * PITCH + kb + t4 + 4]);
            uint32_t a3 = __float_as_uint(ab[(g + 8) * PITCH + kb + t4 + 4]);
            #pragma unroll
            for (int ni = 0; ni < 8; ni++) {
                const int nc = wn * 64 + ni * 8 + g;
                uint32_t b0 = __float_as_uint(Bb[nc * PITCH + kb + t4    ]);
                uint32_t b1 = __float_as_uint(Bb[nc * PITCH + kb + t4 + 4]);
                mma_tf32(acc[ni][0], acc[ni][1], acc[ni][2], acc[ni][3],
                         a0, a1, a2, a3, b0, b1);
            }
        }
    }

    const int r0 = row0 + wm * 16 + g;
    const int r1 = r0 + 8;
    #pragma unroll
    for (int ni = 0; ni < 8; ni++) {
        const int c0 = wn * 64 + ni * 8 + t4 * 2;
        if (r0 < m) *(float2*)(out + (size_t)r0 * H + c0) = make_float2(acc[ni][0], acc[ni][1]);
        if (r1 < m) *(float2*)(out + (size_t)r1 * H + c0) = make_float2(acc[ni][2], acc[ni][3]);
    }
}

extern "C" void kernel_launch(void* const* d_in, const int* in_sizes, int n_in,
                              void* d_out, int out_size) {
    const float* feats = (const float*)d_in[0];
    const float* ctx   = (const float*)d_in[1];
    const void*  lens  = d_in[2];
    const float* Wu    = (const float*)d_in[3];
    const float* bu    = (const float*)d_in[4];
    const float* Wv    = (const float*)d_in[5];
    const float* We    = (const float*)d_in[6];
    const float* Wout  = (const float*)d_in[7];
    float* out = (float*)d_out;

    const int n = in_sizes[0] / H;
    const int b = out_size / H;

    const int smem_out = (3 * A_ST_O + 3 * B_ST) * 4;   // ~124 KB
    cudaFuncSetAttribute(e_gemm_f16,   cudaFuncAttributeMaxDynamicSharedMemorySize, EPS_TOT);
    cudaFuncSetAttribute(out_gemm_mma, cudaFuncAttributeMaxDynamicSharedMemorySize, smem_out);

    float* Wout_r = nullptr; cudaGetSymbolAddress((void**)&Wout_r, g_Wr);

    const int total4 = b * H / 4;
    scan_kernel<<<1, 1024>>>(lens, b, n);
    conv_w_kernel<<<256, 256>>>(Wu, Wv, Wout);
    zero_rst_kernel<<<(total4 + 1023) / 1024, 1024>>>(total4);
    e_gemm_f16<<<(n + 127) / 128, 512, EPS_TOT>>>(feats, ctx, bu, We, n);
    alpha_kernel<<<(b + 7) / 8, 256>>>(b);
    pool_flat_kernel<<<(n + 63) / 64, 256>>>(feats, n);
    out_gemm_mma<<<(b + 31) / 32, 256, smem_out>>>(out, Wout_r, b);
}